// round 15
// baseline (speedup 1.0000x reference)
#include <cuda_runtime.h>
#include <cuda_fp16.h>
#include <cstdint>

#define BS   16
#define NN   1024
#define FIN  128
#define FOUT 64
#define NH   4
#define NEG  0.2f
#define NW   32          // adj words per row
#define L2E  1.4426950408889634f

typedef unsigned int       u32;
typedef unsigned long long u64;

// ---- scratch ----
__device__ __half    g_hpT[(size_t)BS*NH*FOUT*NN];     // 8 MB [bh][o][j] K-major fp16
__device__ unsigned  g_adj[(size_t)BS*NN*NW];          // 2 MB bitmask
__device__ float4    g_sE [BS*NH*NN];   // (src, 2^-k*e^src, 2^-k*e^.2src, -)  k=rint(src*log2e)
__device__ float4    g_dFF[BS*NH*NN];   // (dst, e^dst, e^.2dst, -)

__device__ __forceinline__ float fast_ex2(float x) {
    float r; asm("ex2.approx.f32 %0, %1;" : "=f"(r) : "f"(x)); return r;
}
__device__ __forceinline__ float fast_rcp(float x) {
    float r; asm("rcp.approx.f32 %0, %1;" : "=f"(r) : "f"(x)); return r;
}
// tanh(x) = 1 - 2/(e^{2x}+1);  ex2/rcp approx err ~2^-22 => abs err ~5e-7
__device__ __forceinline__ float fast_tanh(float x) {
    float e = fast_ex2(x * (2.0f * L2E));
    return fmaf(-2.0f, fast_rcp(e + 1.0f), 1.0f);
}

// ---------------------------------------------------------------------------
// Kernel 1: pack adjacency -> bitmask. One warp packs 256 ints (MLP=8).
// ---------------------------------------------------------------------------
__global__ void __launch_bounds__(256) pack_adj_kernel(const int* __restrict__ adj) {
    int warp = (blockIdx.x * blockDim.x + threadIdx.x) >> 5;
    int lane = threadIdx.x & 31;
    size_t base = (size_t)warp * 256;
    int v0 = adj[base +   0 + lane]; int v1 = adj[base +  32 + lane];
    int v2 = adj[base +  64 + lane]; int v3 = adj[base +  96 + lane];
    int v4 = adj[base + 128 + lane]; int v5 = adj[base + 160 + lane];
    int v6 = adj[base + 192 + lane]; int v7 = adj[base + 224 + lane];
    unsigned m0 = __ballot_sync(~0u, v0 != 0), m1 = __ballot_sync(~0u, v1 != 0);
    unsigned m2 = __ballot_sync(~0u, v2 != 0), m3 = __ballot_sync(~0u, v3 != 0);
    unsigned m4 = __ballot_sync(~0u, v4 != 0), m5 = __ballot_sync(~0u, v5 != 0);
    unsigned m6 = __ballot_sync(~0u, v6 != 0), m7 = __ballot_sync(~0u, v7 != 0);
    if (lane == 0) {
        uint4* o = (uint4*)&g_adj[(size_t)warp * 8];
        o[0] = make_uint4(m0, m1, m2, m3);
        o[1] = make_uint4(m4, m5, m6, m7);
    }
}

// ---------------------------------------------------------------------------
// Kernel 2: h_prime GEMM + fast-tanh + src/dst tables; writes TRANSPOSED fp16
// hp (K-major B operand). src table entries computed as ex2(ps*L2E - k):
// exact 2^-k row rescale folded into the exponent (cancels in num/S).
// ---------------------------------------------------------------------------
__global__ void __launch_bounds__(256) hp_kernel(
    const float* __restrict__ h, const float* __restrict__ w,
    const float* __restrict__ a_src, const float* __restrict__ a_dst)
{
    int b = blockIdx.z, hd = blockIdx.y, nt = blockIdx.x;
    __shared__ float w_sh[FIN][FOUT];      // 32 KB
    __shared__ float stage[32][65];        // transpose staging
    __shared__ float as_sh[FOUT], ad_sh[FOUT];

    int t = threadIdx.x;
    for (int idx = t; idx < FIN * FOUT; idx += 256)
        w_sh[idx >> 6][idx & 63] = w[hd * FIN * FOUT + idx];
    if (t < FOUT) { as_sh[t] = a_src[hd * FOUT + t]; ad_sh[t] = a_dst[hd * FOUT + t]; }
    __syncthreads();

    int nl = t >> 3, og = t & 7;
    int n = nt * 32 + nl;
    const float* hrow = h + ((size_t)b * NN + n) * FIN;

    float acc[8] = {0.f,0.f,0.f,0.f,0.f,0.f,0.f,0.f};
    #pragma unroll 8
    for (int f = 0; f < FIN; f++) {
        float hv = __ldg(hrow + f);
        const float4* wr = (const float4*)&w_sh[f][og * 8];
        float4 w0 = wr[0], w1 = wr[1];
        acc[0] += hv * w0.x; acc[1] += hv * w0.y;
        acc[2] += hv * w0.z; acc[3] += hv * w0.w;
        acc[4] += hv * w1.x; acc[5] += hv * w1.y;
        acc[6] += hv * w1.z; acc[7] += hv * w1.w;
    }
    #pragma unroll
    for (int k = 0; k < 8; k++) stage[nl][og * 8 + k] = acc[k];

    float ps = 0.f, pd = 0.f;
    #pragma unroll
    for (int k = 0; k < 8; k++) {
        float tv = fast_tanh(acc[k]);
        ps += tv * as_sh[og * 8 + k];
        pd += tv * ad_sh[og * 8 + k];
    }
    #pragma unroll
    for (int off = 4; off; off >>= 1) {
        ps += __shfl_down_sync(~0u, ps, off, 8);
        pd += __shfl_down_sync(~0u, pd, off, 8);
    }
    if (og == 0) {
        int idx = (b * NH + hd) * NN + n;
        // 2^-k rescale folded into the exponent: e^ps * 2^-k = ex2(ps*L2E - k)
        float kf = rintf(ps * L2E);
        g_sE [idx] = make_float4(ps, fast_ex2(fmaf(ps, L2E, -kf)),
                                     fast_ex2(fmaf(NEG * ps, L2E, -kf)), 0.f);
        g_dFF[idx] = make_float4(pd, fast_ex2(pd * L2E),
                                     fast_ex2(NEG * pd * L2E), 0.f);
    }
    __syncthreads();

    // transpose + fp16 convert: thread -> (o = t>>2, 8-n chunk c = t&3)
    {
        int o = t >> 2, c = t & 3;
        int bh64 = (b * NH + hd) * FOUT;
        u32 uh[4];
        #pragma unroll
        for (int q = 0; q < 4; q++) {
            float p0 = stage[c * 8 + q * 2][o];
            float p1 = stage[c * 8 + q * 2 + 1][o];
            __half2 hh = __floats2half2_rn(p0, p1);
            uh[q] = *(u32*)&hh;
        }
        size_t off = (size_t)(bh64 + o) * NN + nt * 32 + c * 8;
        *(uint4*)&g_hpT[off] = make_uint4(uh[0], uh[1], uh[2], uh[3]);
    }
}

// ---------------------------------------------------------------------------
// Kernel 3: attention via mma.sync m16n8k16 fp16. P single fp16 (rn, row
// rescaled); hp single fp16. TWO jt tiles per pipeline step, 3-stage
// cp.async pipeline. All 4 LDMX4 + dffs LDS hoisted to the TOP of each ks
// so the ~60-cyc P-generation chain covers the ldmatrix latency.
// ---------------------------------------------------------------------------
#define BSTRIDE 40                       // fp16 per smem B row (ldmatrix conflict-free)
#define HALFB   (64 * BSTRIDE * 2)       // bytes per single-jt B tile (5120)
#define STEPB   (2 * HALFB)              // bytes per stage (2 jt)

#define MMA_F16(C, A, b0, b1)                                                  \
    asm volatile("mma.sync.aligned.m16n8k16.row.col.f32.f16.f16.f32 "          \
        "{%0,%1,%2,%3}, {%4,%5,%6,%7}, {%8,%9}, {%0,%1,%2,%3};"                \
        : "+f"((C)[0]), "+f"((C)[1]), "+f"((C)[2]), "+f"((C)[3])               \
        : "r"((A)[0]), "r"((A)[1]), "r"((A)[2]), "r"((A)[3]), "r"(b0), "r"(b1))

#define LDMX4(r0, r1, r2, r3, a)                                               \
    asm volatile("ldmatrix.sync.aligned.m8n8.x4.shared.b16 {%0,%1,%2,%3}, [%4];" \
        : "=r"(r0), "=r"(r1), "=r"(r2), "=r"(r3) : "r"(a))

#define CP16(dst, src) \
    asm volatile("cp.async.cg.shared.global [%0], [%1], 16;" :: "r"(dst), "l"(src) : "memory")
#define CP_COMMIT() asm volatile("cp.async.commit_group;" ::: "memory")
#define CP_WAIT1()  asm volatile("cp.async.wait_group 1;" ::: "memory")

// pack two fp32 -> fp16x2 (first src -> HIGH half, matching A-frag k order)
#define PK16(dst, hi, lo) \
    asm("cvt.rn.f16x2.f32 %0, %1, %2;" : "=r"(dst) : "f"(hi), "f"(lo))

__global__ void __launch_bounds__(256, 2) attn_mma_kernel(
    const float* __restrict__ bias, float* __restrict__ out)
{
    __shared__ __align__(16) __half Bt[3][2 * 64 * BSTRIDE];  // 30.7 KB
    __shared__ __align__(16) float4 dffs[3][64];              // 3 KB

    int t = threadIdx.x;
    int lane = t & 31, w = t >> 5;
    int q = lane & 3, g = lane >> 2;
    int b = blockIdx.z, hd = blockIdx.y, it = blockIdx.x;
    int i0 = it * 128;
    int bh = (b * NH + hd) * NN;
    int bh64 = (b * NH + hd) * FOUT;

    int ia = i0 + w * 16 + g;
    int ib = ia + 8;
    float4 sea = g_sE[bh + ia];
    float4 seb = g_sE[bh + ib];
    const unsigned* awa_p = g_adj + (size_t)(b * NN + ia) * NW;
    const unsigned* awb_p = g_adj + (size_t)(b * NN + ib) * NW;

    float Sa = 0.f, Sb = 0.f;
    float C[8][4];
    #pragma unroll
    for (int ot = 0; ot < 8; ot++) {
        C[ot][0] = 0.f; C[ot][1] = 0.f; C[ot][2] = 0.f; C[ot][3] = 0.f;
    }

    // staging: row = o (t>>2), seg = 16B chunk (t&3)
    int srow = t >> 2, sseg = t & 3;
    const uint4* gsrc = (const uint4*)(g_hpT + (size_t)(bh64 + srow) * NN);
    u32 sBt  = (u32)__cvta_generic_to_shared(Bt);
    u32 sDff = (u32)__cvta_generic_to_shared(dffs);
    u32 doff = (u32)(srow * BSTRIDE + sseg * 8) * 2;
    const float4* dsrc = (const float4*)(g_dFF + bh) + t;   // valid when t<64

    // ldmatrix per-lane term: n-row = (l&7)+((l>>4)&1)*8, k-add = ((l>>3)&1)*8
    u32 lmterm = (u32)((((lane & 7) + ((lane >> 4) & 1) * 8) * BSTRIDE
                        + ((lane >> 3) & 1) * 8) * 2);

    // one stage = two jt tiles (K=64)
    #define ISSUE_STAGE(s, step) do {                                          \
        int _j0 = 2 * (step);                                                  \
        CP16(sBt + (u32)(s) * STEPB + doff,         gsrc + _j0 * 4 + sseg);    \
        CP16(sBt + (u32)(s) * STEPB + HALFB + doff, gsrc + (_j0 + 1) * 4 + sseg); \
        if (t < 64) CP16(sDff + (u32)(s) * 1024 + (u32)t * 16, dsrc + (step) * 64); \
    } while (0)

    ISSUE_STAGE(0, 0); CP_COMMIT();
    ISSUE_STAGE(1, 1); CP_COMMIT();

    unsigned awa0 = __ldg(awa_p),     awb0 = __ldg(awb_p);
    unsigned awa1 = __ldg(awa_p + 1), awb1 = __ldg(awb_p + 1);

    for (int m = 0; m < 16; m++) {
        int s = m % 3;
        // pending groups here: {g_m, g_m+1}; wait_group 1 => stage s complete
        CP_WAIT1();
        __syncthreads();   // ALL threads done with stage (m-1)%3 => safe to overwrite
        if (m < 14) { int sn = (m + 2) % 3; ISSUE_STAGE(sn, m + 2); }
        CP_COMMIT();

        unsigned awc[2][2] = {{awa0, awb0}, {awa1, awb1}};
        int nm = (m < 15) ? m + 1 : 15;
        awa0 = __ldg(awa_p + 2 * nm);     awb0 = __ldg(awb_p + 2 * nm);
        awa1 = __ldg(awa_p + 2 * nm + 1); awb1 = __ldg(awb_p + 2 * nm + 1);

        #pragma unroll
        for (int hh = 0; hh < 2; hh++) {
            unsigned awa_c = awc[hh][0], awb_c = awc[hh][1];
            u32 btb = sBt + (u32)s * STEPB + (u32)hh * HALFB + lmterm;
            const float4* dfp = &dffs[s][hh * 32];

            #pragma unroll
            for (int ks = 0; ks < 2; ks++) {
                int jb = ks * 16;
                // ---- hoisted loads: dffs + ALL ldmatrix BEFORE the P chain ----
                float4 d0 = dfp[jb + 2 * q];
                float4 d1 = dfp[jb + 2 * q + 1];
                float4 d2 = dfp[jb + 2 * q + 8];
                float4 d3 = dfp[jb + 2 * q + 9];
                u32 hb[16];
                #pragma unroll
                for (int pr = 0; pr < 4; pr++) {
                    u32 aoff = (u32)((pr * 16 * BSTRIDE + ks * 16) * 2);
                    LDMX4(hb[pr*4], hb[pr*4+1], hb[pr*4+2], hb[pr*4+3], btb + aoff);
                }

                float pa[4], pb[4];
                {
                    float x;
                    x = sea.x + d0.x; pa[0] = (x >= 0.f) ? sea.y * d0.y : sea.z * d0.z;
                    x = sea.x + d1.x; pa[1] = (x >= 0.f) ? sea.y * d1.y : sea.z * d1.z;
                    x = sea.x + d2.x; pa[2] = (x >= 0.f) ? sea.y * d2.y : sea.z * d2.z;
                    x = sea.x + d3.x; pa[3] = (x >= 0.f) ? sea.y * d3.y : sea.z * d3.z;
                    x = seb.x + d0.x; pb[0] = (x >= 0.f) ? seb.y * d0.y : seb.z * d0.z;
                    x = seb.x + d1.x; pb[1] = (x >= 0.f) ? seb.y * d1.y : seb.z * d1.z;
                    x = seb.x + d2.x; pb[2] = (x >= 0.f) ? seb.y * d2.y : seb.z * d2.z;
                    x = seb.x + d3.x; pb[3] = (x >= 0.f) ? seb.y * d3.y : seb.z * d3.z;
                }
                pa[0] = ((awa_c >> (jb + 2*q    )) & 1u) ? pa[0] : 0.f;
                pa[1] = ((awa_c >> (jb + 2*q + 1)) & 1u) ? pa[1] : 0.f;
                pa[2] = ((awa_c >> (jb + 2*q + 8)) & 1u) ? pa[2] : 0.f;
                pa[3] = ((awa_c >> (jb + 2*q + 9)) & 1u) ? pa[3] : 0.f;
                pb[0] = ((awb_c >> (jb + 2*q    )) & 1u) ? pb[0] : 0.f;
                pb[1] = ((awb_c >> (jb + 2*q + 1)) & 1u) ? pb[1] : 0.f;
                pb[2] = ((awb_c >> (jb + 2*q + 8)) & 1u) ? pb[2] : 0.f;
                pb[3] = ((awb_c >> (jb + 2*q + 9)) & 1u) ? pb[3] : 0.f;
                Sa += pa[0] + pa[1] + pa[2] + pa[3];
                Sb += pb[0] + pb[1] + pb[2] + pb[3];

                // A fragments: single fp16 (rn)
                u32 a[4];
                PK16(a[0], pa[1], pa[0]);   // row g,   k pair lo
                PK16(a[1], pb[1], pb[0]);   // row g+8, k pair lo
                PK16(a[2], pa[3], pa[2]);   // row g,   k pair hi
                PK16(a[3], pb[3], pb[2]);   // row g+8, k pair hi

                #pragma unroll
                for (int pr = 0; pr < 4; pr++) {
                    MMA_F16(C[pr * 2],     a, hb[pr*4],     hb[pr*4 + 1]);
                    MMA_F16(C[pr * 2 + 1], a, hb[pr*4 + 2], hb[pr*4 + 3]);
                }
            }
        }
    }

    // reduce S across the quad (j-coverage split over q)
    Sa += __shfl_xor_sync(~0u, Sa, 1); Sa += __shfl_xor_sync(~0u, Sa, 2);
    Sb += __shfl_xor_sync(~0u, Sb, 1); Sb += __shfl_xor_sync(~0u, Sb, 2);
    float inva = 1.0f / Sa, invb = 1.0f / Sb;

    float* oa = out + ((size_t)bh + ia) * FOUT;
    float* ob = out + ((size_t)bh + ib) * FOUT;
    #pragma unroll
    for (int ot = 0; ot < 8; ot++) {
        int col = ot * 8 + 2 * q;
        float2 bv = __ldg((const float2*)(bias + col));
        *(float2*)(oa + col) = make_float2(C[ot][0] * inva + bv.x,
                                           C[ot][1] * inva + bv.y);
        *(float2*)(ob + col) = make_float2(C[ot][2] * invb + bv.x,
                                           C[ot][3] * invb + bv.y);
    }
}

// ---------------------------------------------------------------------------
extern "C" void kernel_launch(void* const* d_in, const int* in_sizes, int n_in,
                              void* d_out, int out_size)
{
    const float* h     = (const float*)d_in[0];
    const int*   adj   = (const int*)  d_in[1];
    const float* w     = (const float*)d_in[2];
    const float* a_src = (const float*)d_in[3];
    const float* a_dst = (const float*)d_in[4];
    const float* bias  = (const float*)d_in[5];
    float* out = (float*)d_out;

    // order: hp first (diagnostic: puts hp_kernel in ncu's fixed capture slot)
    hp_kernel<<<dim3(NN / 32, NH, BS), 256>>>(h, w, a_src, a_dst);
    pack_adj_kernel<<<(BS * NN * NN) / 2048, 256>>>(adj);
    attn_mma_kernel<<<dim3(NN / 128, NH, BS), 256>>>(bias, out);
}

// round 16
// speedup vs baseline: 1.5014x; 1.5014x over previous
#include <cuda_runtime.h>
#include <cuda_fp16.h>
#include <cstdint>

#define BS   16
#define NN   1024
#define FIN  128
#define FOUT 64
#define NH   4
#define NEG  0.2f
#define NW   32          // adj words per row
#define L2E  1.4426950408889634f

typedef unsigned int       u32;
typedef unsigned long long u64;

// ---- scratch ----
__device__ __half    g_hpT[(size_t)BS*NH*FOUT*NN];     // 8 MB [bh][o][j] K-major fp16
__device__ unsigned  g_adj[(size_t)BS*NN*NW];          // 2 MB bitmask
__device__ float4    g_sE [BS*NH*NN];   // (src, 2^-k*e^src, 2^-k*e^.2src, -)  k=rint(src*log2e)
__device__ float4    g_dFF[BS*NH*NN];   // (dst, e^dst, e^.2dst, -)

__device__ __forceinline__ float fast_ex2(float x) {
    float r; asm("ex2.approx.f32 %0, %1;" : "=f"(r) : "f"(x)); return r;
}
__device__ __forceinline__ float fast_rcp(float x) {
    float r; asm("rcp.approx.f32 %0, %1;" : "=f"(r) : "f"(x)); return r;
}
// tanh(x) = 1 - 2/(e^{2x}+1);  ex2/rcp approx err ~2^-22 => abs err ~5e-7
__device__ __forceinline__ float fast_tanh(float x) {
    float e = fast_ex2(x * (2.0f * L2E));
    return fmaf(-2.0f, fast_rcp(e + 1.0f), 1.0f);
}

// ---------------------------------------------------------------------------
// Kernel 1: pack adjacency -> bitmask. One warp packs 256 ints (MLP=8).
// ---------------------------------------------------------------------------
__global__ void __launch_bounds__(256) pack_adj_kernel(const int* __restrict__ adj) {
    int warp = (blockIdx.x * blockDim.x + threadIdx.x) >> 5;
    int lane = threadIdx.x & 31;
    size_t base = (size_t)warp * 256;
    int v0 = adj[base +   0 + lane]; int v1 = adj[base +  32 + lane];
    int v2 = adj[base +  64 + lane]; int v3 = adj[base +  96 + lane];
    int v4 = adj[base + 128 + lane]; int v5 = adj[base + 160 + lane];
    int v6 = adj[base + 192 + lane]; int v7 = adj[base + 224 + lane];
    unsigned m0 = __ballot_sync(~0u, v0 != 0), m1 = __ballot_sync(~0u, v1 != 0);
    unsigned m2 = __ballot_sync(~0u, v2 != 0), m3 = __ballot_sync(~0u, v3 != 0);
    unsigned m4 = __ballot_sync(~0u, v4 != 0), m5 = __ballot_sync(~0u, v5 != 0);
    unsigned m6 = __ballot_sync(~0u, v6 != 0), m7 = __ballot_sync(~0u, v7 != 0);
    if (lane == 0) {
        uint4* o = (uint4*)&g_adj[(size_t)warp * 8];
        o[0] = make_uint4(m0, m1, m2, m3);
        o[1] = make_uint4(m4, m5, m6, m7);
    }
}

// ---------------------------------------------------------------------------
// Kernel 2: h_prime GEMM + fast-tanh + src/dst tables; writes TRANSPOSED fp16
// hp (K-major B operand). L1 fix: w staged as split float4 arrays w_lo/w_hi
// [128][8] so the per-warp LDS.128 at og*16B is bank-conflict-free (was
// 2-way conflicted at og*32B in the [128][64] layout); h loaded as float4
// (4x fewer LDG). Arithmetic order identical to previous rounds.
// ---------------------------------------------------------------------------
__global__ void __launch_bounds__(256) hp_kernel(
    const float* __restrict__ h, const float* __restrict__ w,
    const float* __restrict__ a_src, const float* __restrict__ a_dst)
{
    int b = blockIdx.z, hd = blockIdx.y, nt = blockIdx.x;
    __shared__ float4 w_lo[FIN][8];        // 16 KB: w[f][og*8 .. og*8+3]
    __shared__ float4 w_hi[FIN][8];        // 16 KB: w[f][og*8+4 .. og*8+7]
    __shared__ float  stage[32][65];       // transpose staging
    __shared__ float  as_sh[FOUT], ad_sh[FOUT];

    int t = threadIdx.x;
    for (int idx = t; idx < FIN * FOUT; idx += 256) {
        int f = idx >> 6, o = idx & 63;
        int og = o >> 3, r = o & 7;
        float v = w[hd * FIN * FOUT + idx];
        if (r < 4) ((float*)&w_lo[f][og])[r]     = v;
        else       ((float*)&w_hi[f][og])[r - 4] = v;
    }
    if (t < FOUT) { as_sh[t] = a_src[hd * FOUT + t]; ad_sh[t] = a_dst[hd * FOUT + t]; }
    __syncthreads();

    int nl = t >> 3, og = t & 7;
    int n = nt * 32 + nl;
    const float4* hrow4 = (const float4*)(h + ((size_t)b * NN + n) * FIN);

    float acc[8] = {0.f,0.f,0.f,0.f,0.f,0.f,0.f,0.f};
    #pragma unroll 8
    for (int ff = 0; ff < 32; ff++) {
        float4 hv4 = __ldg(hrow4 + ff);
        #pragma unroll
        for (int j = 0; j < 4; j++) {
            float hv = (j == 0) ? hv4.x : (j == 1) ? hv4.y : (j == 2) ? hv4.z : hv4.w;
            int f = ff * 4 + j;
            float4 wl = w_lo[f][og];
            float4 wh = w_hi[f][og];
            acc[0] += hv * wl.x; acc[1] += hv * wl.y;
            acc[2] += hv * wl.z; acc[3] += hv * wl.w;
            acc[4] += hv * wh.x; acc[5] += hv * wh.y;
            acc[6] += hv * wh.z; acc[7] += hv * wh.w;
        }
    }
    #pragma unroll
    for (int k = 0; k < 8; k++) stage[nl][og * 8 + k] = acc[k];

    float ps = 0.f, pd = 0.f;
    #pragma unroll
    for (int k = 0; k < 8; k++) {
        float tv = fast_tanh(acc[k]);
        ps += tv * as_sh[og * 8 + k];
        pd += tv * ad_sh[og * 8 + k];
    }
    #pragma unroll
    for (int off = 4; off; off >>= 1) {
        ps += __shfl_down_sync(~0u, ps, off, 8);
        pd += __shfl_down_sync(~0u, pd, off, 8);
    }
    if (og == 0) {
        int idx = (b * NH + hd) * NN + n;
        // 2^-k rescale folded into the exponent: e^ps * 2^-k = ex2(ps*L2E - k)
        float kf = rintf(ps * L2E);
        g_sE [idx] = make_float4(ps, fast_ex2(fmaf(ps, L2E, -kf)),
                                     fast_ex2(fmaf(NEG * ps, L2E, -kf)), 0.f);
        g_dFF[idx] = make_float4(pd, fast_ex2(pd * L2E),
                                     fast_ex2(NEG * pd * L2E), 0.f);
    }
    __syncthreads();

    // transpose + fp16 convert: thread -> (o = t>>2, 8-n chunk c = t&3)
    {
        int o = t >> 2, c = t & 3;
        int bh64 = (b * NH + hd) * FOUT;
        u32 uh[4];
        #pragma unroll
        for (int q = 0; q < 4; q++) {
            float p0 = stage[c * 8 + q * 2][o];
            float p1 = stage[c * 8 + q * 2 + 1][o];
            __half2 hh = __floats2half2_rn(p0, p1);
            uh[q] = *(u32*)&hh;
        }
        size_t off = (size_t)(bh64 + o) * NN + nt * 32 + c * 8;
        *(uint4*)&g_hpT[off] = make_uint4(uh[0], uh[1], uh[2], uh[3]);
    }
}

// ---------------------------------------------------------------------------
// Kernel 3: attention via mma.sync m16n8k16 fp16. P single fp16 (rn, row
// rescaled); hp single fp16. TWO jt tiles per pipeline step, 3-stage
// cp.async pipeline, LDMX4/dffs hoisted above the P chain. (Unchanged.)
// ---------------------------------------------------------------------------
#define BSTRIDE 40                       // fp16 per smem B row (ldmatrix conflict-free)
#define HALFB   (64 * BSTRIDE * 2)       // bytes per single-jt B tile (5120)
#define STEPB   (2 * HALFB)              // bytes per stage (2 jt)

#define MMA_F16(C, A, b0, b1)                                                  \
    asm volatile("mma.sync.aligned.m16n8k16.row.col.f32.f16.f16.f32 "          \
        "{%0,%1,%2,%3}, {%4,%5,%6,%7}, {%8,%9}, {%0,%1,%2,%3};"                \
        : "+f"((C)[0]), "+f"((C)[1]), "+f"((C)[2]), "+f"((C)[3])               \
        : "r"((A)[0]), "r"((A)[1]), "r"((A)[2]), "r"((A)[3]), "r"(b0), "r"(b1))

#define LDMX4(r0, r1, r2, r3, a)                                               \
    asm volatile("ldmatrix.sync.aligned.m8n8.x4.shared.b16 {%0,%1,%2,%3}, [%4];" \
        : "=r"(r0), "=r"(r1), "=r"(r2), "=r"(r3) : "r"(a))

#define CP16(dst, src) \
    asm volatile("cp.async.cg.shared.global [%0], [%1], 16;" :: "r"(dst), "l"(src) : "memory")
#define CP_COMMIT() asm volatile("cp.async.commit_group;" ::: "memory")
#define CP_WAIT1()  asm volatile("cp.async.wait_group 1;" ::: "memory")

// pack two fp32 -> fp16x2 (first src -> HIGH half, matching A-frag k order)
#define PK16(dst, hi, lo) \
    asm("cvt.rn.f16x2.f32 %0, %1, %2;" : "=r"(dst) : "f"(hi), "f"(lo))

__global__ void __launch_bounds__(256, 2) attn_mma_kernel(
    const float* __restrict__ bias, float* __restrict__ out)
{
    __shared__ __align__(16) __half Bt[3][2 * 64 * BSTRIDE];  // 30.7 KB
    __shared__ __align__(16) float4 dffs[3][64];              // 3 KB

    int t = threadIdx.x;
    int lane = t & 31, w = t >> 5;
    int q = lane & 3, g = lane >> 2;
    int b = blockIdx.z, hd = blockIdx.y, it = blockIdx.x;
    int i0 = it * 128;
    int bh = (b * NH + hd) * NN;
    int bh64 = (b * NH + hd) * FOUT;

    int ia = i0 + w * 16 + g;
    int ib = ia + 8;
    float4 sea = g_sE[bh + ia];
    float4 seb = g_sE[bh + ib];
    const unsigned* awa_p = g_adj + (size_t)(b * NN + ia) * NW;
    const unsigned* awb_p = g_adj + (size_t)(b * NN + ib) * NW;

    float Sa = 0.f, Sb = 0.f;
    float C[8][4];
    #pragma unroll
    for (int ot = 0; ot < 8; ot++) {
        C[ot][0] = 0.f; C[ot][1] = 0.f; C[ot][2] = 0.f; C[ot][3] = 0.f;
    }

    // staging: row = o (t>>2), seg = 16B chunk (t&3)
    int srow = t >> 2, sseg = t & 3;
    const uint4* gsrc = (const uint4*)(g_hpT + (size_t)(bh64 + srow) * NN);
    u32 sBt  = (u32)__cvta_generic_to_shared(Bt);
    u32 sDff = (u32)__cvta_generic_to_shared(dffs);
    u32 doff = (u32)(srow * BSTRIDE + sseg * 8) * 2;
    const float4* dsrc = (const float4*)(g_dFF + bh) + t;   // valid when t<64

    // ldmatrix per-lane term: n-row = (l&7)+((l>>4)&1)*8, k-add = ((l>>3)&1)*8
    u32 lmterm = (u32)((((lane & 7) + ((lane >> 4) & 1) * 8) * BSTRIDE
                        + ((lane >> 3) & 1) * 8) * 2);

    // one stage = two jt tiles (K=64)
    #define ISSUE_STAGE(s, step) do {                                          \
        int _j0 = 2 * (step);                                                  \
        CP16(sBt + (u32)(s) * STEPB + doff,         gsrc + _j0 * 4 + sseg);    \
        CP16(sBt + (u32)(s) * STEPB + HALFB + doff, gsrc + (_j0 + 1) * 4 + sseg); \
        if (t < 64) CP16(sDff + (u32)(s) * 1024 + (u32)t * 16, dsrc + (step) * 64); \
    } while (0)

    ISSUE_STAGE(0, 0); CP_COMMIT();
    ISSUE_STAGE(1, 1); CP_COMMIT();

    unsigned awa0 = __ldg(awa_p),     awb0 = __ldg(awb_p);
    unsigned awa1 = __ldg(awa_p + 1), awb1 = __ldg(awb_p + 1);

    for (int m = 0; m < 16; m++) {
        int s = m % 3;
        // pending groups here: {g_m, g_m+1}; wait_group 1 => stage s complete
        CP_WAIT1();
        __syncthreads();   // ALL threads done with stage (m-1)%3 => safe to overwrite
        if (m < 14) { int sn = (m + 2) % 3; ISSUE_STAGE(sn, m + 2); }
        CP_COMMIT();

        unsigned awc[2][2] = {{awa0, awb0}, {awa1, awb1}};
        int nm = (m < 15) ? m + 1 : 15;
        awa0 = __ldg(awa_p + 2 * nm);     awb0 = __ldg(awb_p + 2 * nm);
        awa1 = __ldg(awa_p + 2 * nm + 1); awb1 = __ldg(awb_p + 2 * nm + 1);

        #pragma unroll
        for (int hh = 0; hh < 2; hh++) {
            unsigned awa_c = awc[hh][0], awb_c = awc[hh][1];
            u32 btb = sBt + (u32)s * STEPB + (u32)hh * HALFB + lmterm;
            const float4* dfp = &dffs[s][hh * 32];

            #pragma unroll
            for (int ks = 0; ks < 2; ks++) {
                int jb = ks * 16;
                // ---- hoisted loads: dffs + ALL ldmatrix BEFORE the P chain ----
                float4 d0 = dfp[jb + 2 * q];
                float4 d1 = dfp[jb + 2 * q + 1];
                float4 d2 = dfp[jb + 2 * q + 8];
                float4 d3 = dfp[jb + 2 * q + 9];
                u32 hb[16];
                #pragma unroll
                for (int pr = 0; pr < 4; pr++) {
                    u32 aoff = (u32)((pr * 16 * BSTRIDE + ks * 16) * 2);
                    LDMX4(hb[pr*4], hb[pr*4+1], hb[pr*4+2], hb[pr*4+3], btb + aoff);
                }

                float pa[4], pb[4];
                {
                    float x;
                    x = sea.x + d0.x; pa[0] = (x >= 0.f) ? sea.y * d0.y : sea.z * d0.z;
                    x = sea.x + d1.x; pa[1] = (x >= 0.f) ? sea.y * d1.y : sea.z * d1.z;
                    x = sea.x + d2.x; pa[2] = (x >= 0.f) ? sea.y * d2.y : sea.z * d2.z;
                    x = sea.x + d3.x; pa[3] = (x >= 0.f) ? sea.y * d3.y : sea.z * d3.z;
                    x = seb.x + d0.x; pb[0] = (x >= 0.f) ? seb.y * d0.y : seb.z * d0.z;
                    x = seb.x + d1.x; pb[1] = (x >= 0.f) ? seb.y * d1.y : seb.z * d1.z;
                    x = seb.x + d2.x; pb[2] = (x >= 0.f) ? seb.y * d2.y : seb.z * d2.z;
                    x = seb.x + d3.x; pb[3] = (x >= 0.f) ? seb.y * d3.y : seb.z * d3.z;
                }
                pa[0] = ((awa_c >> (jb + 2*q    )) & 1u) ? pa[0] : 0.f;
                pa[1] = ((awa_c >> (jb + 2*q + 1)) & 1u) ? pa[1] : 0.f;
                pa[2] = ((awa_c >> (jb + 2*q + 8)) & 1u) ? pa[2] : 0.f;
                pa[3] = ((awa_c >> (jb + 2*q + 9)) & 1u) ? pa[3] : 0.f;
                pb[0] = ((awb_c >> (jb + 2*q    )) & 1u) ? pb[0] : 0.f;
                pb[1] = ((awb_c >> (jb + 2*q + 1)) & 1u) ? pb[1] : 0.f;
                pb[2] = ((awb_c >> (jb + 2*q + 8)) & 1u) ? pb[2] : 0.f;
                pb[3] = ((awb_c >> (jb + 2*q + 9)) & 1u) ? pb[3] : 0.f;
                Sa += pa[0] + pa[1] + pa[2] + pa[3];
                Sb += pb[0] + pb[1] + pb[2] + pb[3];

                // A fragments: single fp16 (rn)
                u32 a[4];
                PK16(a[0], pa[1], pa[0]);   // row g,   k pair lo
                PK16(a[1], pb[1], pb[0]);   // row g+8, k pair lo
                PK16(a[2], pa[3], pa[2]);   // row g,   k pair hi
                PK16(a[3], pb[3], pb[2]);   // row g+8, k pair hi

                #pragma unroll
                for (int pr = 0; pr < 4; pr++) {
                    MMA_F16(C[pr * 2],     a, hb[pr*4],     hb[pr*4 + 1]);
                    MMA_F16(C[pr * 2 + 1], a, hb[pr*4 + 2], hb[pr*4 + 3]);
                }
            }
        }
    }

    // reduce S across the quad (j-coverage split over q)
    Sa += __shfl_xor_sync(~0u, Sa, 1); Sa += __shfl_xor_sync(~0u, Sa, 2);
    Sb += __shfl_xor_sync(~0u, Sb, 1); Sb += __shfl_xor_sync(~0u, Sb, 2);
    float inva = 1.0f / Sa, invb = 1.0f / Sb;

    float* oa = out + ((size_t)bh + ia) * FOUT;
    float* ob = out + ((size_t)bh + ib) * FOUT;
    #pragma unroll
    for (int ot = 0; ot < 8; ot++) {
        int col = ot * 8 + 2 * q;
        float2 bv = __ldg((const float2*)(bias + col));
        *(float2*)(oa + col) = make_float2(C[ot][0] * inva + bv.x,
                                           C[ot][1] * inva + bv.y);
        *(float2*)(ob + col) = make_float2(C[ot][2] * invb + bv.x,
                                           C[ot][3] * invb + bv.y);
    }
}

// ---------------------------------------------------------------------------
extern "C" void kernel_launch(void* const* d_in, const int* in_sizes, int n_in,
                              void* d_out, int out_size)
{
    const float* h     = (const float*)d_in[0];
    const int*   adj   = (const int*)  d_in[1];
    const float* w     = (const float*)d_in[2];
    const float* a_src = (const float*)d_in[3];
    const float* a_dst = (const float*)d_in[4];
    const float* bias  = (const float*)d_in[5];
    float* out = (float*)d_out;

    // hp first: keeps hp_kernel in ncu's fixed capture slot to verify the L1 fix
    hp_kernel<<<dim3(NN / 32, NH, BS), 256>>>(h, w, a_src, a_dst);
    pack_adj_kernel<<<(BS * NN * NN) / 2048, 256>>>(adj);
    attn_mma_kernel<<<dim3(NN / 128, NH, BS), 256>>>(bias, out);
}

// round 17
// speedup vs baseline: 2.0104x; 1.3390x over previous
#include <cuda_runtime.h>
#include <cuda_fp16.h>
#include <cstdint>

#define BS   16
#define NN   1024
#define FIN  128
#define FOUT 64
#define NH   4
#define NEG  0.2f
#define NW   32          // adj words per row
#define L2E  1.4426950408889634f

typedef unsigned int       u32;
typedef unsigned long long u64;

// ---- scratch ----
__device__ __half    g_hpT[(size_t)BS*NH*FOUT*NN];     // 8 MB [bh][o][j] K-major fp16
__device__ unsigned  g_adj[(size_t)BS*NN*NW];          // 2 MB bitmask
__device__ float4    g_sE [BS*NH*NN];   // (src, 2^-k*e^src, 2^-k*e^.2src, -)  k=rint(src*log2e)
__device__ float4    g_dFF[BS*NH*NN];   // (dst, e^dst, e^.2dst, -)

__device__ __forceinline__ float fast_ex2(float x) {
    float r; asm("ex2.approx.f32 %0, %1;" : "=f"(r) : "f"(x)); return r;
}
__device__ __forceinline__ float fast_rcp(float x) {
    float r; asm("rcp.approx.f32 %0, %1;" : "=f"(r) : "f"(x)); return r;
}
// tanh(x) = 1 - 2/(e^{2x}+1);  ex2/rcp approx err ~2^-22 => abs err ~5e-7
__device__ __forceinline__ float fast_tanh(float x) {
    float e = fast_ex2(x * (2.0f * L2E));
    return fmaf(-2.0f, fast_rcp(e + 1.0f), 1.0f);
}

// ---------------------------------------------------------------------------
// Kernel 1: pack adjacency -> bitmask. One warp packs 256 ints (MLP=8).
// ---------------------------------------------------------------------------
__global__ void __launch_bounds__(256) pack_adj_kernel(const int* __restrict__ adj) {
    int warp = (blockIdx.x * blockDim.x + threadIdx.x) >> 5;
    int lane = threadIdx.x & 31;
    size_t base = (size_t)warp * 256;
    int v0 = adj[base +   0 + lane]; int v1 = adj[base +  32 + lane];
    int v2 = adj[base +  64 + lane]; int v3 = adj[base +  96 + lane];
    int v4 = adj[base + 128 + lane]; int v5 = adj[base + 160 + lane];
    int v6 = adj[base + 192 + lane]; int v7 = adj[base + 224 + lane];
    unsigned m0 = __ballot_sync(~0u, v0 != 0), m1 = __ballot_sync(~0u, v1 != 0);
    unsigned m2 = __ballot_sync(~0u, v2 != 0), m3 = __ballot_sync(~0u, v3 != 0);
    unsigned m4 = __ballot_sync(~0u, v4 != 0), m5 = __ballot_sync(~0u, v5 != 0);
    unsigned m6 = __ballot_sync(~0u, v6 != 0), m7 = __ballot_sync(~0u, v7 != 0);
    if (lane == 0) {
        uint4* o = (uint4*)&g_adj[(size_t)warp * 8];
        o[0] = make_uint4(m0, m1, m2, m3);
        o[1] = make_uint4(m4, m5, m6, m7);
    }
}

// ---------------------------------------------------------------------------
// Kernel 2: h_prime GEMM + fast-tanh + src/dst tables; writes TRANSPOSED fp16
// hp. 4-row register blocking: each thread computes rows nl, nl+32, nl+64,
// nl+96 so the 2 LDS.128 per f feed 32 FMAs (was 8) -> LDS wavefronts / 4.
// w staged as split float4 arrays (conflict-free); transpose via 4 staged
// passes reusing one 32-row buffer. Per-row arithmetic order unchanged.
// ---------------------------------------------------------------------------
__global__ void __launch_bounds__(256) hp_kernel(
    const float* __restrict__ h, const float* __restrict__ w,
    const float* __restrict__ a_src, const float* __restrict__ a_dst)
{
    int b = blockIdx.z, hd = blockIdx.y, nt = blockIdx.x;   // nt in [0,8)
    __shared__ float4 w_lo[FIN][8];        // 16 KB: w[f][og*8 .. og*8+3]
    __shared__ float4 w_hi[FIN][8];        // 16 KB: w[f][og*8+4 .. og*8+7]
    __shared__ float  stage[32][65];       // transpose staging (reused 4x)
    __shared__ float  as_sh[FOUT], ad_sh[FOUT];

    int t = threadIdx.x;
    for (int idx = t; idx < FIN * FOUT; idx += 256) {
        int f = idx >> 6, o = idx & 63;
        int og = o >> 3, r = o & 7;
        float v = w[hd * FIN * FOUT + idx];
        if (r < 4) ((float*)&w_lo[f][og])[r]     = v;
        else       ((float*)&w_hi[f][og])[r - 4] = v;
    }
    if (t < FOUT) { as_sh[t] = a_src[hd * FOUT + t]; ad_sh[t] = a_dst[hd * FOUT + t]; }
    __syncthreads();

    int nl = t >> 3, og = t & 7;
    int n0 = nt * 128 + nl;                 // rows n0 + 32*r, r = 0..3
    int bh = (b * NH + hd) * NN;
    int bh64 = (b * NH + hd) * FOUT;
    const float4* hrow0 = (const float4*)(h + ((size_t)b * NN + n0) * FIN);
    const float4* hrow1 = hrow0 + 32 * (FIN / 4);
    const float4* hrow2 = hrow1 + 32 * (FIN / 4);
    const float4* hrow3 = hrow2 + 32 * (FIN / 4);

    float acc[4][8];
    #pragma unroll
    for (int r = 0; r < 4; r++)
        #pragma unroll
        for (int k = 0; k < 8; k++) acc[r][k] = 0.f;

    #pragma unroll 4
    for (int ff = 0; ff < 32; ff++) {
        float4 hv0 = __ldg(hrow0 + ff);
        float4 hv1 = __ldg(hrow1 + ff);
        float4 hv2 = __ldg(hrow2 + ff);
        float4 hv3 = __ldg(hrow3 + ff);
        #pragma unroll
        for (int j = 0; j < 4; j++) {
            int f = ff * 4 + j;
            float4 wl = w_lo[f][og];
            float4 wh = w_hi[f][og];
            float a0 = (j == 0) ? hv0.x : (j == 1) ? hv0.y : (j == 2) ? hv0.z : hv0.w;
            float a1 = (j == 0) ? hv1.x : (j == 1) ? hv1.y : (j == 2) ? hv1.z : hv1.w;
            float a2 = (j == 0) ? hv2.x : (j == 1) ? hv2.y : (j == 2) ? hv2.z : hv2.w;
            float a3 = (j == 0) ? hv3.x : (j == 1) ? hv3.y : (j == 2) ? hv3.z : hv3.w;
            acc[0][0] += a0 * wl.x; acc[0][1] += a0 * wl.y;
            acc[0][2] += a0 * wl.z; acc[0][3] += a0 * wl.w;
            acc[0][4] += a0 * wh.x; acc[0][5] += a0 * wh.y;
            acc[0][6] += a0 * wh.z; acc[0][7] += a0 * wh.w;
            acc[1][0] += a1 * wl.x; acc[1][1] += a1 * wl.y;
            acc[1][2] += a1 * wl.z; acc[1][3] += a1 * wl.w;
            acc[1][4] += a1 * wh.x; acc[1][5] += a1 * wh.y;
            acc[1][6] += a1 * wh.z; acc[1][7] += a1 * wh.w;
            acc[2][0] += a2 * wl.x; acc[2][1] += a2 * wl.y;
            acc[2][2] += a2 * wl.z; acc[2][3] += a2 * wl.w;
            acc[2][4] += a2 * wh.x; acc[2][5] += a2 * wh.y;
            acc[2][6] += a2 * wh.z; acc[2][7] += a2 * wh.w;
            acc[3][0] += a3 * wl.x; acc[3][1] += a3 * wl.y;
            acc[3][2] += a3 * wl.z; acc[3][3] += a3 * wl.w;
            acc[3][4] += a3 * wh.x; acc[3][5] += a3 * wh.y;
            acc[3][6] += a3 * wh.z; acc[3][7] += a3 * wh.w;
        }
    }

    // src/dst attention dots + tables, per row
    #pragma unroll
    for (int r = 0; r < 4; r++) {
        float ps = 0.f, pd = 0.f;
        #pragma unroll
        for (int k = 0; k < 8; k++) {
            float tv = fast_tanh(acc[r][k]);
            ps += tv * as_sh[og * 8 + k];
            pd += tv * ad_sh[og * 8 + k];
        }
        #pragma unroll
        for (int off = 4; off; off >>= 1) {
            ps += __shfl_down_sync(~0u, ps, off, 8);
            pd += __shfl_down_sync(~0u, pd, off, 8);
        }
        if (og == 0) {
            int idx = bh + n0 + 32 * r;
            float kf = rintf(ps * L2E);
            g_sE [idx] = make_float4(ps, fast_ex2(fmaf(ps, L2E, -kf)),
                                         fast_ex2(fmaf(NEG * ps, L2E, -kf)), 0.f);
            g_dFF[idx] = make_float4(pd, fast_ex2(pd * L2E),
                                         fast_ex2(NEG * pd * L2E), 0.f);
        }
    }

    // transpose + fp16 convert in 4 staged passes (32 rows each)
    #pragma unroll
    for (int r = 0; r < 4; r++) {
        __syncthreads();
        #pragma unroll
        for (int k = 0; k < 8; k++) stage[nl][og * 8 + k] = acc[r][k];
        __syncthreads();
        int o = t >> 2, c = t & 3;
        u32 uh[4];
        #pragma unroll
        for (int q = 0; q < 4; q++) {
            float p0 = stage[c * 8 + q * 2][o];
            float p1 = stage[c * 8 + q * 2 + 1][o];
            __half2 hh = __floats2half2_rn(p0, p1);
            uh[q] = *(u32*)&hh;
        }
        size_t off = (size_t)(bh64 + o) * NN + nt * 128 + r * 32 + c * 8;
        *(uint4*)&g_hpT[off] = make_uint4(uh[0], uh[1], uh[2], uh[3]);
    }
}

// ---------------------------------------------------------------------------
// Kernel 3: attention via mma.sync m16n8k16 fp16. P single fp16 (rn, row
// rescaled); hp single fp16. TWO jt tiles per pipeline step, 3-stage
// cp.async pipeline, LDMX4/dffs hoisted above the P chain. (Unchanged.)
// ---------------------------------------------------------------------------
#define BSTRIDE 40                       // fp16 per smem B row (ldmatrix conflict-free)
#define HALFB   (64 * BSTRIDE * 2)       // bytes per single-jt B tile (5120)
#define STEPB   (2 * HALFB)              // bytes per stage (2 jt)

#define MMA_F16(C, A, b0, b1)                                                  \
    asm volatile("mma.sync.aligned.m16n8k16.row.col.f32.f16.f16.f32 "          \
        "{%0,%1,%2,%3}, {%4,%5,%6,%7}, {%8,%9}, {%0,%1,%2,%3};"                \
        : "+f"((C)[0]), "+f"((C)[1]), "+f"((C)[2]), "+f"((C)[3])               \
        : "r"((A)[0]), "r"((A)[1]), "r"((A)[2]), "r"((A)[3]), "r"(b0), "r"(b1))

#define LDMX4(r0, r1, r2, r3, a)                                               \
    asm volatile("ldmatrix.sync.aligned.m8n8.x4.shared.b16 {%0,%1,%2,%3}, [%4];" \
        : "=r"(r0), "=r"(r1), "=r"(r2), "=r"(r3) : "r"(a))

#define CP16(dst, src) \
    asm volatile("cp.async.cg.shared.global [%0], [%1], 16;" :: "r"(dst), "l"(src) : "memory")
#define CP_COMMIT() asm volatile("cp.async.commit_group;" ::: "memory")
#define CP_WAIT1()  asm volatile("cp.async.wait_group 1;" ::: "memory")

// pack two fp32 -> fp16x2 (first src -> HIGH half, matching A-frag k order)
#define PK16(dst, hi, lo) \
    asm("cvt.rn.f16x2.f32 %0, %1, %2;" : "=r"(dst) : "f"(hi), "f"(lo))

__global__ void __launch_bounds__(256, 2) attn_mma_kernel(
    const float* __restrict__ bias, float* __restrict__ out)
{
    __shared__ __align__(16) __half Bt[3][2 * 64 * BSTRIDE];  // 30.7 KB
    __shared__ __align__(16) float4 dffs[3][64];              // 3 KB

    int t = threadIdx.x;
    int lane = t & 31, w = t >> 5;
    int q = lane & 3, g = lane >> 2;
    int b = blockIdx.z, hd = blockIdx.y, it = blockIdx.x;
    int i0 = it * 128;
    int bh = (b * NH + hd) * NN;
    int bh64 = (b * NH + hd) * FOUT;

    int ia = i0 + w * 16 + g;
    int ib = ia + 8;
    float4 sea = g_sE[bh + ia];
    float4 seb = g_sE[bh + ib];
    const unsigned* awa_p = g_adj + (size_t)(b * NN + ia) * NW;
    const unsigned* awb_p = g_adj + (size_t)(b * NN + ib) * NW;

    float Sa = 0.f, Sb = 0.f;
    float C[8][4];
    #pragma unroll
    for (int ot = 0; ot < 8; ot++) {
        C[ot][0] = 0.f; C[ot][1] = 0.f; C[ot][2] = 0.f; C[ot][3] = 0.f;
    }

    // staging: row = o (t>>2), seg = 16B chunk (t&3)
    int srow = t >> 2, sseg = t & 3;
    const uint4* gsrc = (const uint4*)(g_hpT + (size_t)(bh64 + srow) * NN);
    u32 sBt  = (u32)__cvta_generic_to_shared(Bt);
    u32 sDff = (u32)__cvta_generic_to_shared(dffs);
    u32 doff = (u32)(srow * BSTRIDE + sseg * 8) * 2;
    const float4* dsrc = (const float4*)(g_dFF + bh) + t;   // valid when t<64

    // ldmatrix per-lane term: n-row = (l&7)+((l>>4)&1)*8, k-add = ((l>>3)&1)*8
    u32 lmterm = (u32)((((lane & 7) + ((lane >> 4) & 1) * 8) * BSTRIDE
                        + ((lane >> 3) & 1) * 8) * 2);

    // one stage = two jt tiles (K=64)
    #define ISSUE_STAGE(s, step) do {                                          \
        int _j0 = 2 * (step);                                                  \
        CP16(sBt + (u32)(s) * STEPB + doff,         gsrc + _j0 * 4 + sseg);    \
        CP16(sBt + (u32)(s) * STEPB + HALFB + doff, gsrc + (_j0 + 1) * 4 + sseg); \
        if (t < 64) CP16(sDff + (u32)(s) * 1024 + (u32)t * 16, dsrc + (step) * 64); \
    } while (0)

    ISSUE_STAGE(0, 0); CP_COMMIT();
    ISSUE_STAGE(1, 1); CP_COMMIT();

    unsigned awa0 = __ldg(awa_p),     awb0 = __ldg(awb_p);
    unsigned awa1 = __ldg(awa_p + 1), awb1 = __ldg(awb_p + 1);

    for (int m = 0; m < 16; m++) {
        int s = m % 3;
        // pending groups here: {g_m, g_m+1}; wait_group 1 => stage s complete
        CP_WAIT1();
        __syncthreads();   // ALL threads done with stage (m-1)%3 => safe to overwrite
        if (m < 14) { int sn = (m + 2) % 3; ISSUE_STAGE(sn, m + 2); }
        CP_COMMIT();

        unsigned awc[2][2] = {{awa0, awb0}, {awa1, awb1}};
        int nm = (m < 15) ? m + 1 : 15;
        awa0 = __ldg(awa_p + 2 * nm);     awb0 = __ldg(awb_p + 2 * nm);
        awa1 = __ldg(awa_p + 2 * nm + 1); awb1 = __ldg(awb_p + 2 * nm + 1);

        #pragma unroll
        for (int hh = 0; hh < 2; hh++) {
            unsigned awa_c = awc[hh][0], awb_c = awc[hh][1];
            u32 btb = sBt + (u32)s * STEPB + (u32)hh * HALFB + lmterm;
            const float4* dfp = &dffs[s][hh * 32];

            #pragma unroll
            for (int ks = 0; ks < 2; ks++) {
                int jb = ks * 16;
                // ---- hoisted loads: dffs + ALL ldmatrix BEFORE the P chain ----
                float4 d0 = dfp[jb + 2 * q];
                float4 d1 = dfp[jb + 2 * q + 1];
                float4 d2 = dfp[jb + 2 * q + 8];
                float4 d3 = dfp[jb + 2 * q + 9];
                u32 hb[16];
                #pragma unroll
                for (int pr = 0; pr < 4; pr++) {
                    u32 aoff = (u32)((pr * 16 * BSTRIDE + ks * 16) * 2);
                    LDMX4(hb[pr*4], hb[pr*4+1], hb[pr*4+2], hb[pr*4+3], btb + aoff);
                }

                float pa[4], pb[4];
                {
                    float x;
                    x = sea.x + d0.x; pa[0] = (x >= 0.f) ? sea.y * d0.y : sea.z * d0.z;
                    x = sea.x + d1.x; pa[1] = (x >= 0.f) ? sea.y * d1.y : sea.z * d1.z;
                    x = sea.x + d2.x; pa[2] = (x >= 0.f) ? sea.y * d2.y : sea.z * d2.z;
                    x = sea.x + d3.x; pa[3] = (x >= 0.f) ? sea.y * d3.y : sea.z * d3.z;
                    x = seb.x + d0.x; pb[0] = (x >= 0.f) ? seb.y * d0.y : seb.z * d0.z;
                    x = seb.x + d1.x; pb[1] = (x >= 0.f) ? seb.y * d1.y : seb.z * d1.z;
                    x = seb.x + d2.x; pb[2] = (x >= 0.f) ? seb.y * d2.y : seb.z * d2.z;
                    x = seb.x + d3.x; pb[3] = (x >= 0.f) ? seb.y * d3.y : seb.z * d3.z;
                }
                pa[0] = ((awa_c >> (jb + 2*q    )) & 1u) ? pa[0] : 0.f;
                pa[1] = ((awa_c >> (jb + 2*q + 1)) & 1u) ? pa[1] : 0.f;
                pa[2] = ((awa_c >> (jb + 2*q + 8)) & 1u) ? pa[2] : 0.f;
                pa[3] = ((awa_c >> (jb + 2*q + 9)) & 1u) ? pa[3] : 0.f;
                pb[0] = ((awb_c >> (jb + 2*q    )) & 1u) ? pb[0] : 0.f;
                pb[1] = ((awb_c >> (jb + 2*q + 1)) & 1u) ? pb[1] : 0.f;
                pb[2] = ((awb_c >> (jb + 2*q + 8)) & 1u) ? pb[2] : 0.f;
                pb[3] = ((awb_c >> (jb + 2*q + 9)) & 1u) ? pb[3] : 0.f;
                Sa += pa[0] + pa[1] + pa[2] + pa[3];
                Sb += pb[0] + pb[1] + pb[2] + pb[3];

                // A fragments: single fp16 (rn)
                u32 a[4];
                PK16(a[0], pa[1], pa[0]);   // row g,   k pair lo
                PK16(a[1], pb[1], pb[0]);   // row g+8, k pair lo
                PK16(a[2], pa[3], pa[2]);   // row g,   k pair hi
                PK16(a[3], pb[3], pb[2]);   // row g+8, k pair hi

                #pragma unroll
                for (int pr = 0; pr < 4; pr++) {
                    MMA_F16(C[pr * 2],     a, hb[pr*4],     hb[pr*4 + 1]);
                    MMA_F16(C[pr * 2 + 1], a, hb[pr*4 + 2], hb[pr*4 + 3]);
                }
            }
        }
    }

    // reduce S across the quad (j-coverage split over q)
    Sa += __shfl_xor_sync(~0u, Sa, 1); Sa += __shfl_xor_sync(~0u, Sa, 2);
    Sb += __shfl_xor_sync(~0u, Sb, 1); Sb += __shfl_xor_sync(~0u, Sb, 2);
    float inva = 1.0f / Sa, invb = 1.0f / Sb;

    float* oa = out + ((size_t)bh + ia) * FOUT;
    float* ob = out + ((size_t)bh + ib) * FOUT;
    #pragma unroll
    for (int ot = 0; ot < 8; ot++) {
        int col = ot * 8 + 2 * q;
        float2 bv = __ldg((const float2*)(bias + col));
        *(float2*)(oa + col) = make_float2(C[ot][0] * inva + bv.x,
                                           C[ot][1] * inva + bv.y);
        *(float2*)(ob + col) = make_float2(C[ot][2] * invb + bv.x,
                                           C[ot][3] * invb + bv.y);
    }
}

// ---------------------------------------------------------------------------
extern "C" void kernel_launch(void* const* d_in, const int* in_sizes, int n_in,
                              void* d_out, int out_size)
{
    const float* h     = (const float*)d_in[0];
    const int*   adj   = (const int*)  d_in[1];
    const float* w     = (const float*)d_in[2];
    const float* a_src = (const float*)d_in[3];
    const float* a_dst = (const float*)d_in[4];
    const float* bias  = (const float*)d_in[5];
    float* out = (float*)d_out;

    // hp first: keeps hp_kernel in ncu's fixed capture slot
    hp_kernel<<<dim3(NN / 128, NH, BS), 256>>>(h, w, a_src, a_dst);
    pack_adj_kernel<<<(BS * NN * NN) / 2048, 256>>>(adj);
    attn_mma_kernel<<<dim3(NN / 128, NH, BS), 256>>>(bias, out);
}